// round 6
// baseline (speedup 1.0000x reference)
#include <cuda_runtime.h>
#include <cuda_bf16.h>
#include <cstdint>

#define NPTS 32768
#define EDG  786432
#define KMAX 64
#define CIN  16
#define CMID 64
#define COUT 64
#define QDIM 1024            // CIN*CMID

__device__ __nv_bfloat16 g_prod_hi[NPTS * QDIM];
__device__ __nv_bfloat16 g_prod_lo[NPTS * QDIM];
__device__ __nv_bfloat16 g_w3t_hi[COUT * QDIM];   // [o][k]
__device__ __nv_bfloat16 g_w3t_lo[COUT * QDIM];
__device__ int g_start[NPTS];
__device__ int g_end[NPTS];

// ---------------- packed fp32 helpers ----------------
#define FMA2(d, a, b, c) \
    asm("fma.rn.f32x2 %0, %1, %2, %3;" : "=l"(d) : "l"(a), "l"(b), "l"(c))
#define PACK2(d, lo, hi) \
    asm("mov.b64 %0, {%1, %2};" : "=l"(d) : "f"(lo), "f"(hi))
#define UNPACK2(lo, hi, s) \
    asm("mov.b64 {%0, %1}, %2;" : "=f"(lo), "=f"(hi) : "l"(s))

struct u64x2 { unsigned long long a, b; };

// ---------------- mma helpers ----------------
__device__ __forceinline__ uint32_t smem_u32(const void* p) {
    uint32_t a;
    asm("{ .reg .u64 t; cvta.to.shared.u64 t, %1; cvt.u32.u64 %0, t; }"
        : "=r"(a) : "l"(p));
    return a;
}

#define LDSM_X4(r0, r1, r2, r3, addr) \
    asm volatile("ldmatrix.sync.aligned.m8n8.x4.shared.b16 {%0,%1,%2,%3}, [%4];" \
        : "=r"(r0), "=r"(r1), "=r"(r2), "=r"(r3) : "r"(addr))

#define MMA16816(d, a, b0, b1) \
    asm volatile("mma.sync.aligned.m16n8k16.row.col.f32.bf16.bf16.f32 " \
        "{%0,%1,%2,%3}, {%4,%5,%6,%7}, {%8,%9}, {%0,%1,%2,%3};" \
        : "+f"((d)[0]), "+f"((d)[1]), "+f"((d)[2]), "+f"((d)[3]) \
        : "r"((a)[0]), "r"((a)[1]), "r"((a)[2]), "r"((a)[3]), "r"(b0), "r"(b1))

__device__ __forceinline__ void split_bf16(float v, __nv_bfloat16& h, __nv_bfloat16& l) {
    h = __float2bfloat16(v);
    l = __float2bfloat16(v - __bfloat162float(h));
}

// ---------------- prep kernels ----------------
__global__ void init_bounds_kernel() {
    int i = blockIdx.x * blockDim.x + threadIdx.x;
    if (i < NPTS) { g_start[i] = 0; g_end[i] = 0; }
}

__global__ void seg_bounds_kernel(const int* __restrict__ out_index) {
    int e = blockIdx.x * blockDim.x + threadIdx.x;
    if (e >= EDG) return;
    int v = out_index[e];
    if (e == 0) {
        g_start[v] = 0;
    } else {
        int pv = out_index[e - 1];
        if (pv != v) { g_start[v] = e; g_end[pv] = e; }
    }
    if (e == EDG - 1) g_end[v] = EDG;
}

__global__ void w3_prep_kernel(const float* __restrict__ W3) {
    int i = blockIdx.x * blockDim.x + threadIdx.x;   // 65536, k-major in W3
    int k = i >> 6, o = i & 63;
    __nv_bfloat16 h, l;
    split_bf16(W3[i], h, l);
    g_w3t_hi[o * QDIM + k] = h;
    g_w3t_lo[o * QDIM + k] = l;
}

__device__ __forceinline__ float celu1(float x) {
    return x > 0.f ? x : (__expf(x) - 1.f);
}

// ---------------- edge kernel: one WARP per point ----------------
__global__ __launch_bounds__(128) void edge_kernel(
    const float* __restrict__ x_in,
    const float* __restrict__ pos_in,
    const float* __restrict__ pos_out,
    const int*   __restrict__ in_index,
    const float* __restrict__ W1,
    const float* __restrict__ W2)
{
    __shared__ __align__(16) float sW1[48];
    __shared__ __align__(16) float sh[4][4][CIN];   // [warp][edge][c]
    __shared__ __align__(16) float sx[4][4][CIN];

    const int tid  = threadIdx.x;
    const int w    = tid >> 5;
    const int lane = tid & 31;
    const int n    = blockIdx.x * 4 + w;

    if (tid < 48) sW1[tid] = W1[tid];

    // W2 columns m0 = lane, m1 = lane+32, packed over c-pairs (q = pair c2q,c2q+1)
    const int m0 = lane, m1 = lane + 32;
    unsigned long long w2a[8], w2b[8];
    #pragma unroll
    for (int q = 0; q < 8; q++) {
        PACK2(w2a[q], W2[(2 * q) * CMID + m0], W2[(2 * q + 1) * CMID + m0]);
        PACK2(w2b[q], W2[(2 * q) * CMID + m1], W2[(2 * q + 1) * CMID + m1]);
    }

    const int s   = g_start[n];
    const int e   = g_end[n];
    const int cnt = e - s;
    const float inv = (cnt > 0) ? (1.f / (float)cnt) : 0.f;
    const int use = (cnt < KMAX) ? cnt : KMAX;

    const float pox = pos_out[3 * n + 0];
    const float poy = pos_out[3 * n + 1];
    const float poz = pos_out[3 * n + 2];

    unsigned long long acc0[8], acc1[8];
    #pragma unroll
    for (int q = 0; q < 8; q++) { acc0[q] = 0ULL; acc1[q] = 0ULL; }

    const int j2 = lane >> 4;
    const int c  = lane & 15;

    __syncthreads();

    for (int base = 0; base < use; base += 4) {
        // ---- stage 1: 2 passes x 2 edges ----
        #pragma unroll
        for (int pass = 0; pass < 2; pass++) {
            int jj = pass * 2 + j2;
            int eidx = base + jj;
            float hv = 0.f, xv = 0.f;
            if (eidx < use) {
                int i = in_index[s + eidx];
                float p0 = pos_in[3 * i + 0] - pox;
                float p1 = pos_in[3 * i + 1] - poy;
                float p2 = pos_in[3 * i + 2] - poz;
                hv = celu1(p0 * sW1[c] + p1 * sW1[16 + c] + p2 * sW1[32 + c]);
                xv = x_in[i * CIN + c] * inv;
            }
            sh[w][jj][c] = hv;
            sx[w][jj][c] = xv;
        }
        __syncwarp();

        // ---- stage 2 ----
        #pragma unroll
        for (int jj = 0; jj < 4; jj++) {
            const float* hj = sh[w][jj];
            const float* xj = sx[w][jj];
            u64x2 hA = *(const u64x2*)(hj);        // pairs q0,q1 (c0..3)
            u64x2 hC = *(const u64x2*)(hj + 4);    // pairs q2,q3 (c4..7)
            u64x2 hB = *(const u64x2*)(hj + 8);    // pairs q4,q5 (c8..11)
            u64x2 hD = *(const u64x2*)(hj + 12);   // pairs q6,q7 (c12..15)
            u64x2 xA = *(const u64x2*)(xj);
            u64x2 xC = *(const u64x2*)(xj + 4);
            u64x2 xB = *(const u64x2*)(xj + 8);
            u64x2 xD = *(const u64x2*)(xj + 12);
            unsigned long long hq[8] = { hA.a, hA.b, hC.a, hC.b,
                                         hB.a, hB.b, hD.a, hD.b };
            unsigned long long xq[8] = { xA.a, xA.b, xC.a, xC.b,
                                         xB.a, xB.b, xD.a, xD.b };

            unsigned long long d0 = 0ULL, d1 = 0ULL;
            #pragma unroll
            for (int q = 0; q < 8; q++) {
                FMA2(d0, hq[q], w2a[q], d0);
                FMA2(d1, hq[q], w2b[q], d1);
            }
            float a0, b0v, a1, b1v;
            UNPACK2(a0, b0v, d0);
            UNPACK2(a1, b1v, d1);
            float Mv0 = celu1(a0 + b0v);
            float Mv1 = celu1(a1 + b1v);
            unsigned long long mp0, mp1;
            PACK2(mp0, Mv0, Mv0);
            PACK2(mp1, Mv1, Mv1);

            #pragma unroll
            for (int q = 0; q < 8; q++) {
                FMA2(acc0[q], xq[q], mp0, acc0[q]);
                FMA2(acc1[q], xq[q], mp1, acc1[q]);
            }
        }
        __syncwarp();
    }

    // acc index q corresponds to c-pair (2q, 2q+1)
    const size_t rbase = (size_t)n * QDIM;
    #pragma unroll
    for (int q = 0; q < 8; q++) {
        float v0, v1, u0, u1;
        UNPACK2(v0, v1, acc0[q]);
        UNPACK2(u0, u1, acc1[q]);
        __nv_bfloat16 hh, ll;
        split_bf16(v0, hh, ll);
        g_prod_hi[rbase + (2 * q) * CMID + m0] = hh;
        g_prod_lo[rbase + (2 * q) * CMID + m0] = ll;
        split_bf16(v1, hh, ll);
        g_prod_hi[rbase + (2 * q + 1) * CMID + m0] = hh;
        g_prod_lo[rbase + (2 * q + 1) * CMID + m0] = ll;
        split_bf16(u0, hh, ll);
        g_prod_hi[rbase + (2 * q) * CMID + m1] = hh;
        g_prod_lo[rbase + (2 * q) * CMID + m1] = ll;
        split_bf16(u1, hh, ll);
        g_prod_hi[rbase + (2 * q + 1) * CMID + m1] = hh;
        g_prod_lo[rbase + (2 * q + 1) * CMID + m1] = ll;
    }
}

// ---------------- tensor-core GEMM via mma.sync ----------------
#define TILE_K   64
#define PAD      8
#define ROWW     (TILE_K + PAD)
#define OFF_A_HI 0
#define OFF_A_LO (128 * ROWW * 2)
#define OFF_B_HI (2 * 128 * ROWW * 2)
#define OFF_B_LO (2 * 128 * ROWW * 2 + 64 * ROWW * 2)
#define GEMM_SMEM (2 * 128 * ROWW * 2 + 2 * 64 * ROWW * 2)

__global__ __launch_bounds__(256) void mma_gemm_kernel(
    const float* __restrict__ b3,
    float* __restrict__ out)
{
    extern __shared__ __align__(16) char smem[];
    const uint32_t sbase = smem_u32(smem);
    const int tid  = threadIdx.x;
    const int wid  = tid >> 5;
    const int lane = tid & 31;
    const int n0   = blockIdx.x * 128;

    const __nv_bfloat16* gA_hi = g_prod_hi + (size_t)n0 * QDIM;
    const __nv_bfloat16* gA_lo = g_prod_lo + (size_t)n0 * QDIM;

    float acc[8][4];
    #pragma unroll
    for (int t = 0; t < 8; t++)
        #pragma unroll
        for (int i = 0; i < 4; i++) acc[t][i] = 0.f;

    const int a_row  = wid * 16 + (lane & 15);
    const int a_koff = (lane >> 4) * 8;
    const int b_n    = (lane & 7) + ((lane & 16) ? 8 : 0);
    const int b_koff = (lane & 8) ? 8 : 0;

    const uint32_t aHiAddr = sbase + OFF_A_HI + (uint32_t)(a_row * ROWW + a_koff) * 2;
    const uint32_t aLoAddr = sbase + OFF_A_LO + (uint32_t)(a_row * ROWW + a_koff) * 2;
    const uint32_t bHiAddr = sbase + OFF_B_HI + (uint32_t)(b_n * ROWW + b_koff) * 2;
    const uint32_t bLoAddr = sbase + OFF_B_LO + (uint32_t)(b_n * ROWW + b_koff) * 2;

    for (int kt = 0; kt < QDIM / TILE_K; kt++) {
        const int k0 = kt * TILE_K;

        #pragma unroll
        for (int it = 0; it < 16; it++) {
            int i = it * 256 + tid;
            int row = i >> 5, kk = i & 31;
            uint32_t dst = (uint32_t)(row * ROWW + kk * 2) * 2;
            size_t src = (size_t)row * QDIM + k0 + kk * 2;
            *(uint32_t*)(smem + OFF_A_HI + dst) = *(const uint32_t*)(gA_hi + src);
            *(uint32_t*)(smem + OFF_A_LO + dst) = *(const uint32_t*)(gA_lo + src);
        }
        #pragma unroll
        for (int it = 0; it < 8; it++) {
            int i = it * 256 + tid;
            int o = i >> 5, kk = i & 31;
            uint32_t dst = (uint32_t)(o * ROWW + kk * 2) * 2;
            size_t src = (size_t)o * QDIM + k0 + kk * 2;
            *(uint32_t*)(smem + OFF_B_HI + dst) = *(const uint32_t*)(g_w3t_hi + src);
            *(uint32_t*)(smem + OFF_B_LO + dst) = *(const uint32_t*)(g_w3t_lo + src);
        }
        __syncthreads();

        #pragma unroll
        for (int ks = 0; ks < 4; ks++) {
            const uint32_t kb = (uint32_t)(ks * 16) * 2;
            uint32_t ah[4], al[4];
            LDSM_X4(ah[0], ah[1], ah[2], ah[3], aHiAddr + kb);
            LDSM_X4(al[0], al[1], al[2], al[3], aLoAddr + kb);

            uint32_t bh[4][4], bl[4][4];
            #pragma unroll
            for (int p = 0; p < 4; p++) {
                const uint32_t nb = (uint32_t)(p * 16 * ROWW) * 2;
                LDSM_X4(bh[p][0], bh[p][1], bh[p][2], bh[p][3], bHiAddr + nb + kb);
                LDSM_X4(bl[p][0], bl[p][1], bl[p][2], bl[p][3], bLoAddr + nb + kb);
            }
            #pragma unroll
            for (int p = 0; p < 4; p++) {
                MMA16816(acc[2 * p],     ah, bh[p][0], bh[p][1]);
                MMA16816(acc[2 * p + 1], ah, bh[p][2], bh[p][3]);
                MMA16816(acc[2 * p],     ah, bl[p][0], bl[p][1]);
                MMA16816(acc[2 * p + 1], ah, bl[p][2], bl[p][3]);
                MMA16816(acc[2 * p],     al, bh[p][0], bh[p][1]);
                MMA16816(acc[2 * p + 1], al, bh[p][2], bh[p][3]);
            }
        }
        __syncthreads();
    }

    const int r0 = n0 + wid * 16 + (lane >> 2);
    const int cbase = (lane & 3) * 2;
    #pragma unroll
    for (int t = 0; t < 8; t++) {
        int col = t * 8 + cbase;
        float b0 = b3[col], b1 = b3[col + 1];
        out[(size_t)r0 * COUT + col]           = acc[t][0] + b0;
        out[(size_t)r0 * COUT + col + 1]       = acc[t][1] + b1;
        out[(size_t)(r0 + 8) * COUT + col]     = acc[t][2] + b0;
        out[(size_t)(r0 + 8) * COUT + col + 1] = acc[t][3] + b1;
    }
}

extern "C" void kernel_launch(void* const* d_in, const int* in_sizes, int n_in,
                              void* d_out, int out_size) {
    const float* x_in      = (const float*)d_in[0];
    const float* pos_in    = (const float*)d_in[1];
    const float* pos_out   = (const float*)d_in[2];
    const int*   in_index  = (const int*)d_in[3];
    const int*   out_index = (const int*)d_in[4];
    const float* W1        = (const float*)d_in[5];
    const float* W2        = (const float*)d_in[6];
    const float* W3        = (const float*)d_in[7];
    const float* b3        = (const float*)d_in[8];
    float* out = (float*)d_out;

    cudaFuncSetAttribute(mma_gemm_kernel,
                         cudaFuncAttributeMaxDynamicSharedMemorySize, GEMM_SMEM);

    init_bounds_kernel<<<NPTS / 256, 256>>>();
    seg_bounds_kernel<<<EDG / 256, 256>>>(out_index);
    w3_prep_kernel<<<(QDIM * COUT) / 256, 256>>>(W3);
    edge_kernel<<<NPTS / 4, 128>>>(x_in, pos_in, pos_out, in_index, W1, W2);
    mma_gemm_kernel<<<NPTS / 128, 256, GEMM_SMEM>>>(b3, out);
}

// round 14
// speedup vs baseline: 1.1390x; 1.1390x over previous
#include <cuda_runtime.h>
#include <cuda_bf16.h>
#include <cstdint>

#define NPTS 32768
#define EDG  786432
#define KMAX 64
#define CIN  16
#define CMID 64
#define COUT 64
#define QDIM 1024            // CIN*CMID

__device__ __nv_bfloat16 g_prod_hi[NPTS * QDIM];
__device__ __nv_bfloat16 g_prod_lo[NPTS * QDIM];
__device__ __nv_bfloat16 g_w3t_hi[COUT * QDIM];   // [o][k]
__device__ __nv_bfloat16 g_w3t_lo[COUT * QDIM];
__device__ int g_start[NPTS];
__device__ int g_end[NPTS];

// ---------------- packed fp32 helpers ----------------
#define FMA2(d, a, b, c) \
    asm("fma.rn.f32x2 %0, %1, %2, %3;" : "=l"(d) : "l"(a), "l"(b), "l"(c))
#define PACK2(d, lo, hi) \
    asm("mov.b64 %0, {%1, %2};" : "=l"(d) : "f"(lo), "f"(hi))
#define UNPACK2(lo, hi, s) \
    asm("mov.b64 {%0, %1}, %2;" : "=f"(lo), "=f"(hi) : "l"(s))

struct __align__(16) u64x2 { unsigned long long a, b; };

// ---------------- mma helpers ----------------
__device__ __forceinline__ uint32_t smem_u32(const void* p) {
    uint32_t a;
    asm("{ .reg .u64 t; cvta.to.shared.u64 t, %1; cvt.u32.u64 %0, t; }"
        : "=r"(a) : "l"(p));
    return a;
}

#define LDSM_X4(r0, r1, r2, r3, addr) \
    asm volatile("ldmatrix.sync.aligned.m8n8.x4.shared.b16 {%0,%1,%2,%3}, [%4];" \
        : "=r"(r0), "=r"(r1), "=r"(r2), "=r"(r3) : "r"(addr))

#define MMA16816(d, a, b0, b1) \
    asm volatile("mma.sync.aligned.m16n8k16.row.col.f32.bf16.bf16.f32 " \
        "{%0,%1,%2,%3}, {%4,%5,%6,%7}, {%8,%9}, {%0,%1,%2,%3};" \
        : "+f"((d)[0]), "+f"((d)[1]), "+f"((d)[2]), "+f"((d)[3]) \
        : "r"((a)[0]), "r"((a)[1]), "r"((a)[2]), "r"((a)[3]), "r"(b0), "r"(b1))

__device__ __forceinline__ void split_bf16(float v, __nv_bfloat16& h, __nv_bfloat16& l) {
    h = __float2bfloat16(v);
    l = __float2bfloat16(v - __bfloat162float(h));
}

// ---------------- prep kernels ----------------
__global__ void init_bounds_kernel() {
    int i = blockIdx.x * blockDim.x + threadIdx.x;
    if (i < NPTS) { g_start[i] = 0; g_end[i] = 0; }
}

__global__ void seg_bounds_kernel(const int* __restrict__ out_index) {
    int e = blockIdx.x * blockDim.x + threadIdx.x;
    if (e >= EDG) return;
    int v = out_index[e];
    if (e == 0) {
        g_start[v] = 0;
    } else {
        int pv = out_index[e - 1];
        if (pv != v) { g_start[v] = e; g_end[pv] = e; }
    }
    if (e == EDG - 1) g_end[v] = EDG;
}

__global__ void w3_prep_kernel(const float* __restrict__ W3) {
    int i = blockIdx.x * blockDim.x + threadIdx.x;   // 65536, k-major in W3
    int k = i >> 6, o = i & 63;
    __nv_bfloat16 h, l;
    split_bf16(W3[i], h, l);
    g_w3t_hi[o * QDIM + k] = h;
    g_w3t_lo[o * QDIM + k] = l;
}

__device__ __forceinline__ float celu1(float x) {
    return x > 0.f ? x : (__expf(x) - 1.f);
}

// ---------------- edge kernel: one block (64 thr) per point, tile of 8 edges ----------------
// Stage 1: threads (j = tid>>4, c = tid&15) compute 2 edges each:
//   sh[jj][c] = celu(pos_local . W1[:,c]),  sx[jj][c] = x_in[i][c]/cnt
// Stage 2: thread tid = m: per edge, dot h.W2[:,m] via 8 FMA2 (LDS.128 reads),
//   Mv = celu(.), acc[c-pairs] += x * Mv via 8 FMA2.
#define ETILE 8
__global__ __launch_bounds__(64) void edge_kernel(
    const float* __restrict__ x_in,
    const float* __restrict__ pos_in,
    const float* __restrict__ pos_out,
    const int*   __restrict__ in_index,
    const float* __restrict__ W1,
    const float* __restrict__ W2)
{
    __shared__ __align__(16) float sW1[48];
    __shared__ __align__(16) float sh[ETILE][CIN];
    __shared__ __align__(16) float sx[ETILE][CIN];

    const int tid = threadIdx.x;
    const int n   = blockIdx.x;

    if (tid < 48) sW1[tid] = W1[tid];

    // W2 column m = tid, packed over c-pairs q=(c2q, c2q+1)
    const int m = tid;
    unsigned long long w2p[8];
    #pragma unroll
    for (int q = 0; q < 8; q++)
        PACK2(w2p[q], W2[(2 * q) * CMID + m], W2[(2 * q + 1) * CMID + m]);

    const int s   = g_start[n];
    const int e   = g_end[n];
    const int cnt = e - s;
    const float inv = (cnt > 0) ? (1.f / (float)cnt) : 0.f;
    const int use = (cnt < KMAX) ? cnt : KMAX;

    const float pox = pos_out[3 * n + 0];
    const float poy = pos_out[3 * n + 1];
    const float poz = pos_out[3 * n + 2];

    unsigned long long accp[8];
    #pragma unroll
    for (int q = 0; q < 8; q++) accp[q] = 0ULL;

    const int j = tid >> 4;
    const int c = tid & 15;

    __syncthreads();

    for (int base = 0; base < use; base += ETILE) {
        // ---- stage 1: each thread handles edges base+j and base+j+4 ----
        #pragma unroll
        for (int t = 0; t < 2; t++) {
            int jj = j + 4 * t;
            int eidx = base + jj;
            float hv = 0.f, xv = 0.f;
            if (eidx < use) {
                int i = in_index[s + eidx];
                float p0 = pos_in[3 * i + 0] - pox;
                float p1 = pos_in[3 * i + 1] - poy;
                float p2 = pos_in[3 * i + 2] - poz;
                hv = celu1(p0 * sW1[c] + p1 * sW1[16 + c] + p2 * sW1[32 + c]);
                xv = x_in[i * CIN + c] * inv;
            }
            sh[jj][c] = hv;
            sx[jj][c] = xv;
        }
        __syncthreads();

        // ---- stage 2: 8 edges; padded edges contribute exactly 0 ----
        #pragma unroll
        for (int jj = 0; jj < ETILE; jj++) {
            const float* hj = sh[jj];
            const float* xj = sx[jj];
            u64x2 h0 = *(const u64x2*)(hj);        // c0..3  -> q0,q1
            u64x2 h1 = *(const u64x2*)(hj + 4);    // c4..7  -> q2,q3
            u64x2 h2 = *(const u64x2*)(hj + 8);    // c8..11 -> q4,q5
            u64x2 h3 = *(const u64x2*)(hj + 12);   // c12..15-> q6,q7

            unsigned long long d = 0ULL;
            FMA2(d, h0.a, w2p[0], d);
            FMA2(d, h0.b, w2p[1], d);
            FMA2(d, h1.a, w2p[2], d);
            FMA2(d, h1.b, w2p[3], d);
            FMA2(d, h2.a, w2p[4], d);
            FMA2(d, h2.b, w2p[5], d);
            FMA2(d, h3.a, w2p[6], d);
            FMA2(d, h3.b, w2p[7], d);

            float dlo, dhi;
            UNPACK2(dlo, dhi, d);
            float Mv = celu1(dlo + dhi);
            unsigned long long mp;
            PACK2(mp, Mv, Mv);

            u64x2 x0 = *(const u64x2*)(xj);
            u64x2 x1 = *(const u64x2*)(xj + 4);
            u64x2 x2 = *(const u64x2*)(xj + 8);
            u64x2 x3 = *(const u64x2*)(xj + 12);
            FMA2(accp[0], x0.a, mp, accp[0]);
            FMA2(accp[1], x0.b, mp, accp[1]);
            FMA2(accp[2], x1.a, mp, accp[2]);
            FMA2(accp[3], x1.b, mp, accp[3]);
            FMA2(accp[4], x2.a, mp, accp[4]);
            FMA2(accp[5], x2.b, mp, accp[5]);
            FMA2(accp[6], x3.a, mp, accp[6]);
            FMA2(accp[7], x3.b, mp, accp[7]);
        }
        __syncthreads();
    }

    const size_t rbase = (size_t)n * QDIM;
    #pragma unroll
    for (int q = 0; q < 8; q++) {
        float lo, hi;
        UNPACK2(lo, hi, accp[q]);
        __nv_bfloat16 hh, ll;
        split_bf16(lo, hh, ll);
        g_prod_hi[rbase + (2 * q) * CMID + tid] = hh;
        g_prod_lo[rbase + (2 * q) * CMID + tid] = ll;
        split_bf16(hi, hh, ll);
        g_prod_hi[rbase + (2 * q + 1) * CMID + tid] = hh;
        g_prod_lo[rbase + (2 * q + 1) * CMID + tid] = ll;
    }
}

// ---------------- tensor-core GEMM via mma.sync ----------------
#define TILE_K   64
#define PAD      8
#define ROWW     (TILE_K + PAD)
#define OFF_A_HI 0
#define OFF_A_LO (128 * ROWW * 2)
#define OFF_B_HI (2 * 128 * ROWW * 2)
#define OFF_B_LO (2 * 128 * ROWW * 2 + 64 * ROWW * 2)
#define GEMM_SMEM (2 * 128 * ROWW * 2 + 2 * 64 * ROWW * 2)

__global__ __launch_bounds__(256) void mma_gemm_kernel(
    const float* __restrict__ b3,
    float* __restrict__ out)
{
    extern __shared__ __align__(16) char smem[];
    const uint32_t sbase = smem_u32(smem);
    const int tid  = threadIdx.x;
    const int wid  = tid >> 5;
    const int lane = tid & 31;
    const int n0   = blockIdx.x * 128;

    const __nv_bfloat16* gA_hi = g_prod_hi + (size_t)n0 * QDIM;
    const __nv_bfloat16* gA_lo = g_prod_lo + (size_t)n0 * QDIM;

    float acc[8][4];
    #pragma unroll
    for (int t = 0; t < 8; t++)
        #pragma unroll
        for (int i = 0; i < 4; i++) acc[t][i] = 0.f;

    const int a_row  = wid * 16 + (lane & 15);
    const int a_koff = (lane >> 4) * 8;
    const int b_n    = (lane & 7) + ((lane & 16) ? 8 : 0);
    const int b_koff = (lane & 8) ? 8 : 0;

    const uint32_t aHiAddr = sbase + OFF_A_HI + (uint32_t)(a_row * ROWW + a_koff) * 2;
    const uint32_t aLoAddr = sbase + OFF_A_LO + (uint32_t)(a_row * ROWW + a_koff) * 2;
    const uint32_t bHiAddr = sbase + OFF_B_HI + (uint32_t)(b_n * ROWW + b_koff) * 2;
    const uint32_t bLoAddr = sbase + OFF_B_LO + (uint32_t)(b_n * ROWW + b_koff) * 2;

    for (int kt = 0; kt < QDIM / TILE_K; kt++) {
        const int k0 = kt * TILE_K;

        #pragma unroll
        for (int it = 0; it < 16; it++) {
            int i = it * 256 + tid;
            int row = i >> 5, kk = i & 31;
            uint32_t dst = (uint32_t)(row * ROWW + kk * 2) * 2;
            size_t src = (size_t)row * QDIM + k0 + kk * 2;
            *(uint32_t*)(smem + OFF_A_HI + dst) = *(const uint32_t*)(gA_hi + src);
            *(uint32_t*)(smem + OFF_A_LO + dst) = *(const uint32_t*)(gA_lo + src);
        }
        #pragma unroll
        for (int it = 0; it < 8; it++) {
            int i = it * 256 + tid;
            int o = i >> 5, kk = i & 31;
            uint32_t dst = (uint32_t)(o * ROWW + kk * 2) * 2;
            size_t src = (size_t)o * QDIM + k0 + kk * 2;
            *(uint32_t*)(smem + OFF_B_HI + dst) = *(const uint32_t*)(g_w3t_hi + src);
            *(uint32_t*)(smem + OFF_B_LO + dst) = *(const uint32_t*)(g_w3t_lo + src);
        }
        __syncthreads();

        #pragma unroll
        for (int ks = 0; ks < 4; ks++) {
            const uint32_t kb = (uint32_t)(ks * 16) * 2;
            uint32_t ah[4], al[4];
            LDSM_X4(ah[0], ah[1], ah[2], ah[3], aHiAddr + kb);
            LDSM_X4(al[0], al[1], al[2], al[3], aLoAddr + kb);

            uint32_t bh[4][4], bl[4][4];
            #pragma unroll
            for (int p = 0; p < 4; p++) {
                const uint32_t nb = (uint32_t)(p * 16 * ROWW) * 2;
                LDSM_X4(bh[p][0], bh[p][1], bh[p][2], bh[p][3], bHiAddr + nb + kb);
                LDSM_X4(bl[p][0], bl[p][1], bl[p][2], bl[p][3], bLoAddr + nb + kb);
            }
            #pragma unroll
            for (int p = 0; p < 4; p++) {
                MMA16816(acc[2 * p],     ah, bh[p][0], bh[p][1]);
                MMA16816(acc[2 * p + 1], ah, bh[p][2], bh[p][3]);
                MMA16816(acc[2 * p],     ah, bl[p][0], bl[p][1]);
                MMA16816(acc[2 * p + 1], ah, bl[p][2], bl[p][3]);
                MMA16816(acc[2 * p],     al, bh[p][0], bh[p][1]);
                MMA16816(acc[2 * p + 1], al, bh[p][2], bh[p][3]);
            }
        }
        __syncthreads();
    }

    const int r0 = n0 + wid * 16 + (lane >> 2);
    const int cbase = (lane & 3) * 2;
    #pragma unroll
    for (int t = 0; t < 8; t++) {
        int col = t * 8 + cbase;
        float b0 = b3[col], b1 = b3[col + 1];
        out[(size_t)r0 * COUT + col]           = acc[t][0] + b0;
        out[(size_t)r0 * COUT + col + 1]       = acc[t][1] + b1;
        out[(size_t)(r0 + 8) * COUT + col]     = acc[t][2] + b0;
        out[(size_t)(r0 + 8) * COUT + col + 1] = acc[t][3] + b1;
    }
}

extern "C" void kernel_launch(void* const* d_in, const int* in_sizes, int n_in,
                              void* d_out, int out_size) {
    const float* x_in      = (const float*)d_in[0];
    const float* pos_in    = (const float*)d_in[1];
    const float* pos_out   = (const float*)d_in[2];
    const int*   in_index  = (const int*)d_in[3];
    const int*   out_index = (const int*)d_in[4];
    const float* W1        = (const float*)d_in[5];
    const float* W2        = (const float*)d_in[6];
    const float* W3        = (const float*)d_in[7];
    const float* b3        = (const float*)d_in[8];
    float* out = (float*)d_out;

    cudaFuncSetAttribute(mma_gemm_kernel,
                         cudaFuncAttributeMaxDynamicSharedMemorySize, GEMM_SMEM);

    init_bounds_kernel<<<NPTS / 256, 256>>>();
    seg_bounds_kernel<<<EDG / 256, 256>>>(out_index);
    w3_prep_kernel<<<(QDIM * COUT) / 256, 256>>>(W3);
    edge_kernel<<<NPTS, 64>>>(x_in, pos_in, pos_out, in_index, W1, W2);
    mma_gemm_kernel<<<NPTS / 128, 256, GEMM_SMEM>>>(b3, out);
}